// round 1
// baseline (speedup 1.0000x reference)
#include <cuda_runtime.h>
#include <cuda_bf16.h>

// Z[b,o] = sum_i X[b,i] * W[i,o] * Werr[idx[b],i,o] + bias[o] * Berr[idx[b],o]
// B=256, IN=512, OUT=512, POOL=1000.
// HBM-bound: ~256 MB gathered Werr stream. Tile 8 batches x 128 out-cols per
// block so W (1 MB, reused by all batches) causes only 32 MB of L2 traffic.

constexpr int BDIM  = 256;   // batch
constexpr int IN    = 512;
constexpr int OUT   = 512;

constexpr int BLK_O   = 128; // output cols per block (32 lanes x float4)
constexpr int BLK_B   = 8;   // batches per block (one warp each)
constexpr int THREADS = 256;

__global__ __launch_bounds__(THREADS, 1)
void aconnect_kernel(const float* __restrict__ X,
                     const float* __restrict__ W,
                     const float* __restrict__ bias,
                     const float* __restrict__ Werr,
                     const float* __restrict__ Berr,
                     const int*   __restrict__ idx,
                     float*       __restrict__ out)
{
    __shared__ float xs[BLK_B][IN];

    const int tid  = threadIdx.x;
    const int lane = tid & 31;
    const int grp  = tid >> 5;                 // warp id == batch-within-block
    const int b0   = blockIdx.y * BLK_B;
    const int o0   = blockIdx.x * BLK_O;

    // Cooperative stage of the 8 X rows (16 KB) into shared.
    #pragma unroll
    for (int k = tid; k < BLK_B * IN; k += THREADS) {
        const int rb = k >> 9;        // k / IN
        const int ci = k & (IN - 1);  // k % IN
        xs[rb][ci] = X[(size_t)(b0 + rb) * IN + ci];
    }
    __syncthreads();

    const int b = b0 + grp;
    const int p = idx[b];
    const int o = o0 + lane * 4;

    const float4* __restrict__ w4 =
        reinterpret_cast<const float4*>(W + o);
    const float4* __restrict__ e4 =
        reinterpret_cast<const float4*>(Werr + (size_t)p * IN * OUT + o);

    float4 acc = make_float4(0.f, 0.f, 0.f, 0.f);

    // Main stream loop: per i, one 16B W load (L1/L2 hit after first warp)
    // and one 16B Werr load (DRAM stream). Unroll for MLP.
    #pragma unroll 8
    for (int i = 0; i < IN; ++i) {
        const float  x = xs[grp][i];
        const float4 w = w4[i * (OUT / 4)];
        const float4 e = e4[i * (OUT / 4)];
        acc.x = fmaf(x * w.x, e.x, acc.x);
        acc.y = fmaf(x * w.y, e.y, acc.y);
        acc.z = fmaf(x * w.z, e.z, acc.z);
        acc.w = fmaf(x * w.w, e.w, acc.w);
    }

    // Noisy bias epilogue.
    const float4 bi = *reinterpret_cast<const float4*>(bias + o);
    const float4 be = *reinterpret_cast<const float4*>(Berr + (size_t)p * OUT + o);
    acc.x = fmaf(bi.x, be.x, acc.x);
    acc.y = fmaf(bi.y, be.y, acc.y);
    acc.z = fmaf(bi.z, be.z, acc.z);
    acc.w = fmaf(bi.w, be.w, acc.w);

    *reinterpret_cast<float4*>(out + (size_t)b * OUT + o) = acc;
}

extern "C" void kernel_launch(void* const* d_in, const int* in_sizes, int n_in,
                              void* d_out, int out_size)
{
    const float* X    = (const float*)d_in[0];  // [256, 512]
    const float* W    = (const float*)d_in[1];  // [512, 512]
    const float* bias = (const float*)d_in[2];  // [512]
    const float* Werr = (const float*)d_in[3];  // [1000, 512, 512]
    const float* Berr = (const float*)d_in[4];  // [1000, 512]
    const int*   idx  = (const int*)  d_in[5];  // [256]
    float*       out  = (float*)d_out;          // [256, 512]

    dim3 grid(OUT / BLK_O, BDIM / BLK_B);       // (4, 32) = 128 blocks
    aconnect_kernel<<<grid, THREADS>>>(X, W, bias, Werr, Berr, idx, out);
}

// round 3
// speedup vs baseline: 1.5150x; 1.5150x over previous
#include <cuda_runtime.h>
#include <cuda_bf16.h>

// Z[b,o] = sum_i X[b,i] * W[i,o] * Werr[idx[b],i,o] + bias[o] * Berr[idx[b],o]
// B=256, IN=512, OUT=512, POOL=1000.
// HBM-stream bound (~256 MB gathered Werr). R1 lesson: latency-bound at
// 8 warps/SM — KSPLIT=2 gives 2048 warps over 256 blocks (~2/SM).

constexpr int BDIM   = 256;
constexpr int IN     = 512;
constexpr int OUT    = 512;

constexpr int BLK_O   = 128;          // 32 lanes x float4
constexpr int BLK_B   = 4;            // batches per block
constexpr int KSPLIT  = 2;            // k-halves per (batch, o-tile)
constexpr int KCH     = IN / KSPLIT;  // 256 iters per warp
constexpr int THREADS = BLK_B * KSPLIT * 32;  // 256

__global__ __launch_bounds__(THREADS, 2)
void aconnect_kernel(const float* __restrict__ X,
                     const float* __restrict__ W,
                     const float* __restrict__ bias,
                     const float* __restrict__ Werr,
                     const float* __restrict__ Berr,
                     const int*   __restrict__ idx,
                     float*       __restrict__ out)
{
    __shared__ float  xs[BLK_B][IN];
    __shared__ float4 red[THREADS / 32][32];

    const int tid  = threadIdx.x;
    const int lane = tid & 31;
    const int w    = tid >> 5;            // warp id in [0,8)
    const int bl   = w & (BLK_B - 1);     // batch-within-block
    const int kh   = w >> 2;              // k-half (0 or 1)

    const int b0 = blockIdx.y * BLK_B;
    const int o0 = blockIdx.x * BLK_O;
    const int b  = b0 + bl;
    const int o  = o0 + lane * 4;

    // Hoist the pool-index load so the Werr base address is ready before the
    // staging barrier releases.
    const int p = idx[b];

    // Stage the 4 X rows (8 KB) into shared.
    #pragma unroll
    for (int k = tid; k < BLK_B * IN; k += THREADS) {
        const int rb = k >> 9;         // k / IN
        const int ci = k & (IN - 1);   // k % IN
        xs[rb][ci] = X[(size_t)(b0 + rb) * IN + ci];
    }
    __syncthreads();

    const float4* __restrict__ w4 =
        reinterpret_cast<const float4*>(W + (size_t)kh * KCH * OUT + o);
    const float4* __restrict__ e4 =
        reinterpret_cast<const float4*>(Werr + (size_t)p * IN * OUT
                                             + (size_t)kh * KCH * OUT + o);
    const float* __restrict__ xrow = &xs[bl][kh * KCH];

    float4 acc = make_float4(0.f, 0.f, 0.f, 0.f);

    // Per iter: one 16B W load (L1/L2 hit) + one 16B Werr load (DRAM stream).
    #pragma unroll 8
    for (int i = 0; i < KCH; ++i) {
        const float  x  = xrow[i];
        const float4 ww = w4[i * (OUT / 4)];
        const float4 ee = e4[i * (OUT / 4)];
        acc.x = fmaf(x * ww.x, ee.x, acc.x);
        acc.y = fmaf(x * ww.y, ee.y, acc.y);
        acc.z = fmaf(x * ww.z, ee.z, acc.z);
        acc.w = fmaf(x * ww.w, ee.w, acc.w);
    }

    // Cross-k-half reduction in shared.
    red[w][lane] = acc;
    __syncthreads();

    if (kh == 0) {
        const float4 other = red[w + BLK_B][lane];
        acc.x += other.x;  acc.y += other.y;
        acc.z += other.z;  acc.w += other.w;

        // Noisy bias epilogue.
        const float4 bi = *reinterpret_cast<const float4*>(bias + o);
        const float4 be = *reinterpret_cast<const float4*>(Berr + (size_t)p * OUT + o);
        acc.x = fmaf(bi.x, be.x, acc.x);
        acc.y = fmaf(bi.y, be.y, acc.y);
        acc.z = fmaf(bi.z, be.z, acc.z);
        acc.w = fmaf(bi.w, be.w, acc.w);

        *reinterpret_cast<float4*>(out + (size_t)b * OUT + o) = acc;
    }
}

extern "C" void kernel_launch(void* const* d_in, const int* in_sizes, int n_in,
                              void* d_out, int out_size)
{
    const float* X    = (const float*)d_in[0];  // [256, 512]
    const float* W    = (const float*)d_in[1];  // [512, 512]
    const float* bias = (const float*)d_in[2];  // [512]
    const float* Werr = (const float*)d_in[3];  // [1000, 512, 512]
    const float* Berr = (const float*)d_in[4];  // [1000, 512]
    const int*   idx  = (const int*)  d_in[5];  // [256]
    float*       out  = (float*)d_out;          // [256, 512]

    dim3 grid(OUT / BLK_O, BDIM / BLK_B);       // (4, 64) = 256 blocks
    aconnect_kernel<<<grid, THREADS>>>(X, W, bias, Werr, Berr, idx, out);
}